// round 13
// baseline (speedup 1.0000x reference)
#include <cuda_runtime.h>
#include <cuda_bf16.h>
#include <cstdint>

// ---------------------------------------------------------------------------
// Scratch (device globals; no allocation allowed)
// ---------------------------------------------------------------------------
__device__ float g_y[4096 * 1024];            // tanh(x@[W1;W2]^T + b), 16MB

static __device__ __forceinline__ uint32_t s2u(const void* p) {
    return (uint32_t)__cvta_generic_to_shared(p);
}
static __device__ __forceinline__ float frcp(float x) {
    float r;
    asm("rcp.approx.ftz.f32 %0, %1;" : "=f"(r) : "f"(x));
    return r;
}

// ---- packed f32x2 ops (Blackwell) ----
static __device__ __forceinline__ uint64_t fma2(uint64_t a, uint64_t b, uint64_t c) {
    uint64_t d;
    asm("fma.rn.f32x2 %0, %1, %2, %3;" : "=l"(d) : "l"(a), "l"(b), "l"(c));
    return d;
}
static __device__ __forceinline__ uint64_t add2(uint64_t a, uint64_t b) {
    uint64_t d;
    asm("add.rn.f32x2 %0, %1, %2;" : "=l"(d) : "l"(a), "l"(b));
    return d;
}
static __device__ __forceinline__ uint64_t mul2(uint64_t a, uint64_t b) {
    uint64_t d;
    asm("mul.rn.f32x2 %0, %1, %2;" : "=l"(d) : "l"(a), "l"(b));
    return d;
}
static __device__ __forceinline__ uint64_t bcast2(float x) {
    uint64_t d;
    asm("mov.b64 %0, {%1, %1};" : "=l"(d) : "f"(x));
    return d;
}
static __device__ __forceinline__ uint64_t pack2(float x, float y) {
    uint64_t d;
    asm("mov.b64 %0, {%1, %2};" : "=l"(d) : "f"(x), "f"(y));
    return d;
}
static __device__ __forceinline__ float2 unpack2(uint64_t v) {
    float2 r;
    asm("mov.b64 {%0, %1}, %2;" : "=f"(r.x), "=f"(r.y) : "l"(v));
    return r;
}

// ---------------------------------------------------------------------------
// Phase 1: split-bf16 GEMM on mma.sync (HMMA.16816). Unchanged (~41us).
// ---------------------------------------------------------------------------
#define ROWB 144
#define TILEB (128 * ROWB)
#define SM_AH 0
#define SM_AL TILEB
#define SM_BH (2 * TILEB)
#define SM_BL (3 * TILEB)
#define SM_TOTAL (4 * TILEB)

#define LDM_X4(r0, r1, r2, r3, addr) \
    asm volatile("ldmatrix.sync.aligned.m8n8.x4.shared.b16 {%0,%1,%2,%3}, [%4];" \
                 : "=r"(r0), "=r"(r1), "=r"(r2), "=r"(r3) : "r"(addr))

#define MMA_BF16(c, a, b) \
    asm volatile("mma.sync.aligned.m16n8k16.row.col.f32.bf16.bf16.f32 " \
                 "{%0,%1,%2,%3}, {%4,%5,%6,%7}, {%8,%9}, {%0,%1,%2,%3};" \
                 : "+f"((c)[0]), "+f"((c)[1]), "+f"((c)[2]), "+f"((c)[3]) \
                 : "r"((a)[0]), "r"((a)[1]), "r"((a)[2]), "r"((a)[3]), \
                   "r"((b)[0]), "r"((b)[1]))

static __device__ __forceinline__ void split4(float4 v, uint2& hh, uint2& ll) {
    __nv_bfloat162 h01 = __float22bfloat162_rn(make_float2(v.x, v.y));
    __nv_bfloat162 h23 = __float22bfloat162_rn(make_float2(v.z, v.w));
    float2 hf01 = __bfloat1622float2(h01);
    float2 hf23 = __bfloat1622float2(h23);
    __nv_bfloat162 l01 = __float22bfloat162_rn(make_float2(v.x - hf01.x, v.y - hf01.y));
    __nv_bfloat162 l23 = __float22bfloat162_rn(make_float2(v.z - hf23.x, v.w - hf23.y));
    hh.x = *(uint32_t*)&h01; hh.y = *(uint32_t*)&h23;
    ll.x = *(uint32_t*)&l01; ll.y = *(uint32_t*)&l23;
}

__global__ __launch_bounds__(256, 2) void gemm_tc_kernel(
    const float* __restrict__ x,
    const float* __restrict__ W1, const float* __restrict__ W2,
    const float* __restrict__ b1, const float* __restrict__ b2)
{
    extern __shared__ char sm[];
    const uint32_t sb = s2u(sm);
    const int tid  = threadIdx.x;
    const int wid  = tid >> 5;
    const int lane = tid & 31;

    const int mBase = blockIdx.x * 128;
    const int nBase = blockIdx.y * 128;

    const float* __restrict__ Wsrc = (nBase < 512) ? W1 : W2;
    const int nOff = nBase & 511;

    const int wm = wid & 1;
    const int wn = wid >> 1;

    const int lr  = lane & 7;
    const int ls3 = (lane >> 3) & 1;
    const int ls4 = (lane >> 4) & 1;

    float acc[4][4][4];
#pragma unroll
    for (int mi = 0; mi < 4; mi++)
#pragma unroll
        for (int ni = 0; ni < 4; ni++)
#pragma unroll
            for (int f = 0; f < 4; f++) acc[mi][ni][f] = 0.0f;

    for (int kc = 0; kc < 8; kc++) {
        __syncthreads();

        float4 va[8];
#pragma unroll
        for (int t = 0; t < 8; t++) {
            int idx = tid + t * 256;
            int row = idx >> 4;
            int c4  = idx & 15;
            va[t] = *(const float4*)(x + (size_t)(mBase + row) * 512 + kc * 64 + c4 * 4);
        }
        float4 vb[8];
#pragma unroll
        for (int t = 0; t < 8; t++) {
            int idx = tid + t * 256;
            int row = idx >> 4;
            int c4  = idx & 15;
            vb[t] = *(const float4*)(Wsrc + (size_t)(nOff + row) * 512 + kc * 64 + c4 * 4);
        }
#pragma unroll
        for (int t = 0; t < 8; t++) {
            int idx = tid + t * 256;
            int row = idx >> 4;
            int c4  = idx & 15;
            uint32_t off = row * ROWB + c4 * 8;
            uint2 hh, ll;
            split4(va[t], hh, ll);
            *(uint2*)(sm + SM_AH + off) = hh;
            *(uint2*)(sm + SM_AL + off) = ll;
        }
#pragma unroll
        for (int t = 0; t < 8; t++) {
            int idx = tid + t * 256;
            int row = idx >> 4;
            int c4  = idx & 15;
            uint32_t off = row * ROWB + c4 * 8;
            uint2 hh, ll;
            split4(vb[t], hh, ll);
            *(uint2*)(sm + SM_BH + off) = hh;
            *(uint2*)(sm + SM_BL + off) = ll;
        }
        __syncthreads();

#pragma unroll
        for (int ks = 0; ks < 4; ks++) {
            const int kb = ks * 16;
            uint32_t aoff = (uint32_t)((wm * 64 + ls3 * 8 + lr) * ROWB + (kb + ls4 * 8) * 2);
            uint32_t boff = (uint32_t)((wn * 32 + ls4 * 8 + lr) * ROWB + (kb + ls3 * 8) * 2);

            uint32_t bhf[4][2], blf[4][2];
#pragma unroll
            for (int nb = 0; nb < 2; nb++) {
                LDM_X4(bhf[2 * nb][0], bhf[2 * nb][1], bhf[2 * nb + 1][0], bhf[2 * nb + 1][1],
                       sb + SM_BH + boff + nb * 16 * ROWB);
                LDM_X4(blf[2 * nb][0], blf[2 * nb][1], blf[2 * nb + 1][0], blf[2 * nb + 1][1],
                       sb + SM_BL + boff + nb * 16 * ROWB);
            }

            uint32_t af[4][4];
#pragma unroll
            for (int mi = 0; mi < 4; mi++)
                LDM_X4(af[mi][0], af[mi][1], af[mi][2], af[mi][3],
                       sb + SM_AH + aoff + mi * 16 * ROWB);
#pragma unroll
            for (int mi = 0; mi < 4; mi++)
#pragma unroll
                for (int ni = 0; ni < 4; ni++)
                    MMA_BF16(acc[mi][ni], af[mi], bhf[ni]);
#pragma unroll
            for (int mi = 0; mi < 4; mi++)
#pragma unroll
                for (int ni = 0; ni < 4; ni++)
                    MMA_BF16(acc[mi][ni], af[mi], blf[ni]);
#pragma unroll
            for (int mi = 0; mi < 4; mi++)
                LDM_X4(af[mi][0], af[mi][1], af[mi][2], af[mi][3],
                       sb + SM_AL + aoff + mi * 16 * ROWB);
#pragma unroll
            for (int mi = 0; mi < 4; mi++)
#pragma unroll
                for (int ni = 0; ni < 4; ni++)
                    MMA_BF16(acc[mi][ni], af[mi], bhf[ni]);
        }
    }

    const float* bias = (nBase < 512) ? (b1 + nBase) : (b2 + (nBase - 512));
#pragma unroll
    for (int mi = 0; mi < 4; mi++) {
#pragma unroll
        for (int ni = 0; ni < 4; ni++) {
            int m = mBase + wm * 64 + mi * 16 + (lane >> 2);
            int nl = wn * 32 + ni * 8 + (lane & 3) * 2;
            float bv0 = __ldg(bias + nl);
            float bv1 = __ldg(bias + nl + 1);
            float2 o0, o1;
            o0.x = tanhf(acc[mi][ni][0] + bv0);
            o0.y = tanhf(acc[mi][ni][1] + bv1);
            o1.x = tanhf(acc[mi][ni][2] + bv0);
            o1.y = tanhf(acc[mi][ni][3] + bv1);
            *(float2*)(g_y + (size_t)m * 1024 + nBase + nl)       = o0;
            *(float2*)(g_y + (size_t)(m + 8) * 1024 + nBase + nl) = o1;
        }
    }
}

// ---------------------------------------------------------------------------
// Phase 2a: init out = bout (so both attn halves can atomicAdd)
// ---------------------------------------------------------------------------
__global__ __launch_bounds__(256) void init_out_kernel(
    const float* __restrict__ bout, float* __restrict__ out)
{
    int i = blockIdx.x * 256 + threadIdx.x;   // float4 index, 130048 total
    const float bo = __ldg(bout);
    float4 v = make_float4(bo, bo, bo, bo);
    ((float4*)out)[i] = v;
}

// ---------------------------------------------------------------------------
// Phase 2b: additive attention, a-dimension SPLIT across 2 CTAs per tile.
// grid (4,2,64): z = b*2 + half; each CTA sums 4 of the 8 a-chunks and
// atomicAdds partials into out. 512 CTAs -> ~3 CTAs/SM resident (regs<=80,
// smem 35KB) => ~6 warps/SMSP to hide the rcp/fma dependency chains.
// Inner loop identical to the measured R9/R11 version.
// ---------------------------------------------------------------------------
#define ACH   64
#define STRJ  34
#define STRI  68
#define AT_SMEM ((2 * ACH * STRJ + ACH * STRI + ACH) * 4)   // 35072 B

__global__ __launch_bounds__(256, 3) void attn_kernel(
    const float* __restrict__ Wout,
    float* __restrict__ out)
{
    extern __shared__ float smf[];
    float* s_p  = smf;                           // [ACH][STRJ]
    float* s_wp = smf + ACH * STRJ;              // [ACH][STRJ]
    float* s_u  = smf + 2 * ACH * STRJ;          // [ACH][STRI]
    float* s_w  = s_u + ACH * STRI;              // [ACH]

    const int zb   = blockIdx.z;
    const int b    = zb >> 1;
    const int half = zb & 1;
    const int j0 = blockIdx.x * 32;
    const int i0 = blockIdx.y * 64;

    const int tid = threadIdx.x;
    const int jg  = tid & 15;          // j = j0 + 2*jg + {0,1}
    const int ig  = tid >> 4;          // i = i0 + 4*ig + {0..3}

    const float* __restrict__ Y = g_y + (size_t)b * 128 * 1024;

    const int fa = tid & 63;
    const int fr = tid >> 6;

    const uint64_t ONE2 = 0x3F8000003F800000ull;
    uint64_t acc2[2][2] = {{0ull, 0ull}, {0ull, 0ull}};

    for (int cc = half * 4; cc < half * 4 + 4; cc++) {
        const int ac = cc * ACH;
        const float w = __ldg(Wout + ac + fa);

        __syncthreads();
#pragma unroll
        for (int t = 0; t < 8; t++) {
            int r = fr + t * 4;
            float p = Y[(size_t)(j0 + r) * 1024 + ac + fa];
            s_p [fa * STRJ + r] = p;
            s_wp[fa * STRJ + r] = w * p;
        }
#pragma unroll
        for (int t = 0; t < 16; t++) {
            int r  = fr + t * 4;
            int r2 = i0 + r + 1;
            r2 = (r2 > 127) ? 127 : r2;
            s_u[fa * STRI + r] = Y[(size_t)r2 * 1024 + 512 + ac + fa];
        }
        if (tid < ACH) s_w[tid] = w;
        __syncthreads();

#pragma unroll 2
        for (int a = 0; a < ACH; a += 2) {
            float2 wpair = *(const float2*)&s_w[a];
            float2 pA  = *(const float2*)&s_p [ a      * STRJ + jg * 2];
            float2 pB  = *(const float2*)&s_p [(a + 1) * STRJ + jg * 2];
            float2 wpA = *(const float2*)&s_wp[ a      * STRJ + jg * 2];
            float2 wpB = *(const float2*)&s_wp[(a + 1) * STRJ + jg * 2];
            ulonglong2 uA = *(const ulonglong2*)&s_u[ a      * STRI + ig * 4];
            ulonglong2 uB = *(const ulonglong2*)&s_u[(a + 1) * STRI + ig * 4];

            uint64_t pAb[2]  = {bcast2(pA.x),  bcast2(pA.y)};
            uint64_t pBb[2]  = {bcast2(pB.x),  bcast2(pB.y)};
            uint64_t wpAb[2] = {bcast2(wpA.x), bcast2(wpA.y)};
            uint64_t wpBb[2] = {bcast2(wpB.x), bcast2(wpB.y)};
            uint64_t wAb = bcast2(wpair.x);
            uint64_t wBb = bcast2(wpair.y);
            uint64_t uAp[2] = {uA.x, uA.y};
            uint64_t uBp[2] = {uB.x, uB.y};
            uint64_t wuA[2] = {mul2(wAb, uAp[0]), mul2(wAb, uAp[1])};
            uint64_t wuB[2] = {mul2(wBb, uBp[0]), mul2(wBb, uBp[1])};

#pragma unroll
            for (int j = 0; j < 2; j++)
#pragma unroll
                for (int ip = 0; ip < 2; ip++) {
                    uint64_t d1 = fma2(uAp[ip], pAb[j], ONE2);
                    uint64_t d2 = fma2(uBp[ip], pBb[j], ONE2);
                    uint64_t n1 = add2(wuA[ip], wpAb[j]);
                    uint64_t n2 = add2(wuB[ip], wpBb[j]);
                    uint64_t t  = mul2(d1, d2);
                    float2 tf = unpack2(t);
                    uint64_t r  = pack2(frcp(tf.x), frcp(tf.y));
                    uint64_t e  = mul2(n1, d2);
                    e = fma2(n2, d1, e);
                    acc2[j][ip] = fma2(e, r, acc2[j][ip]);
                }
        }
    }

    // accumulate partial sums into out (init kernel pre-filled with bout)
#pragma unroll
    for (int ip = 0; ip < 2; ip++) {
        float2 aj0 = unpack2(acc2[0][ip]);
        float2 aj1 = unpack2(acc2[1][ip]);
#pragma unroll
        for (int l = 0; l < 2; l++) {
            int i = i0 + ig * 4 + ip * 2 + l;
            if (i < 127) {
                float* dst = out + ((size_t)b * 127 + i) * 128 + j0 + jg * 2;
                atomicAdd(dst,     (l == 0 ? aj0.x : aj0.y));
                atomicAdd(dst + 1, (l == 0 ? aj1.x : aj1.y));
            }
        }
    }
}

// ---------------------------------------------------------------------------
extern "C" void kernel_launch(void* const* d_in, const int* in_sizes, int n_in,
                              void* d_out, int out_size)
{
    const float* x    = (const float*)d_in[0];
    const float* W1   = (const float*)d_in[1];
    const float* b1   = (const float*)d_in[2];
    const float* W2   = (const float*)d_in[3];
    const float* b2   = (const float*)d_in[4];
    const float* Wout = (const float*)d_in[5];
    const float* bout = (const float*)d_in[6];
    float* out = (float*)d_out;

    static bool attr_set = false;
    if (!attr_set) {
        cudaFuncSetAttribute(gemm_tc_kernel,
                             cudaFuncAttributeMaxDynamicSharedMemorySize, SM_TOTAL);
        cudaFuncSetAttribute(attn_kernel,
                             cudaFuncAttributeMaxDynamicSharedMemorySize, AT_SMEM);
        attr_set = true;
    }

    gemm_tc_kernel<<<dim3(32, 8), 256, SM_TOTAL>>>(x, W1, W2, b1, b2);

    // out = 32*127*128 = 520192 floats = 130048 float4
    init_out_kernel<<<130048 / 256, 256>>>(bout, out);

    attn_kernel<<<dim3(4, 2, 64), 256, AT_SMEM>>>(Wout, out);
}

// round 14
// speedup vs baseline: 1.0203x; 1.0203x over previous
#include <cuda_runtime.h>
#include <cuda_bf16.h>
#include <cstdint>

// ---------------------------------------------------------------------------
// Scratch (device globals; no allocation allowed)
// ---------------------------------------------------------------------------
__device__ float g_y[4096 * 1024];            // tanh(x@[W1;W2]^T + b), 16MB

static __device__ __forceinline__ uint32_t s2u(const void* p) {
    return (uint32_t)__cvta_generic_to_shared(p);
}
static __device__ __forceinline__ float frcp(float x) {
    float r;
    asm("rcp.approx.ftz.f32 %0, %1;" : "=f"(r) : "f"(x));
    return r;
}

// ---- packed f32x2 ops (Blackwell) ----
static __device__ __forceinline__ uint64_t fma2(uint64_t a, uint64_t b, uint64_t c) {
    uint64_t d;
    asm("fma.rn.f32x2 %0, %1, %2, %3;" : "=l"(d) : "l"(a), "l"(b), "l"(c));
    return d;
}
static __device__ __forceinline__ uint64_t add2(uint64_t a, uint64_t b) {
    uint64_t d;
    asm("add.rn.f32x2 %0, %1, %2;" : "=l"(d) : "l"(a), "l"(b));
    return d;
}
static __device__ __forceinline__ uint64_t mul2(uint64_t a, uint64_t b) {
    uint64_t d;
    asm("mul.rn.f32x2 %0, %1, %2;" : "=l"(d) : "l"(a), "l"(b));
    return d;
}
static __device__ __forceinline__ uint64_t bcast2(float x) {
    uint64_t d;
    asm("mov.b64 %0, {%1, %1};" : "=l"(d) : "f"(x));
    return d;
}
static __device__ __forceinline__ uint64_t pack2(float x, float y) {
    uint64_t d;
    asm("mov.b64 %0, {%1, %2};" : "=l"(d) : "f"(x), "f"(y));
    return d;
}
static __device__ __forceinline__ float2 unpack2(uint64_t v) {
    float2 r;
    asm("mov.b64 {%0, %1}, %2;" : "=f"(r.x), "=f"(r.y) : "l"(v));
    return r;
}

// ---------------------------------------------------------------------------
// Phase 1: split-bf16 GEMM on mma.sync (HMMA.16816). Unchanged (~41-43us).
// ---------------------------------------------------------------------------
#define ROWB 144
#define TILEB (128 * ROWB)
#define SM_AH 0
#define SM_AL TILEB
#define SM_BH (2 * TILEB)
#define SM_BL (3 * TILEB)
#define SM_TOTAL (4 * TILEB)

#define LDM_X4(r0, r1, r2, r3, addr) \
    asm volatile("ldmatrix.sync.aligned.m8n8.x4.shared.b16 {%0,%1,%2,%3}, [%4];" \
                 : "=r"(r0), "=r"(r1), "=r"(r2), "=r"(r3) : "r"(addr))

#define MMA_BF16(c, a, b) \
    asm volatile("mma.sync.aligned.m16n8k16.row.col.f32.bf16.bf16.f32 " \
                 "{%0,%1,%2,%3}, {%4,%5,%6,%7}, {%8,%9}, {%0,%1,%2,%3};" \
                 : "+f"((c)[0]), "+f"((c)[1]), "+f"((c)[2]), "+f"((c)[3]) \
                 : "r"((a)[0]), "r"((a)[1]), "r"((a)[2]), "r"((a)[3]), \
                   "r"((b)[0]), "r"((b)[1]))

static __device__ __forceinline__ void split4(float4 v, uint2& hh, uint2& ll) {
    __nv_bfloat162 h01 = __float22bfloat162_rn(make_float2(v.x, v.y));
    __nv_bfloat162 h23 = __float22bfloat162_rn(make_float2(v.z, v.w));
    float2 hf01 = __bfloat1622float2(h01);
    float2 hf23 = __bfloat1622float2(h23);
    __nv_bfloat162 l01 = __float22bfloat162_rn(make_float2(v.x - hf01.x, v.y - hf01.y));
    __nv_bfloat162 l23 = __float22bfloat162_rn(make_float2(v.z - hf23.x, v.w - hf23.y));
    hh.x = *(uint32_t*)&h01; hh.y = *(uint32_t*)&h23;
    ll.x = *(uint32_t*)&l01; ll.y = *(uint32_t*)&l23;
}

__global__ __launch_bounds__(256, 2) void gemm_tc_kernel(
    const float* __restrict__ x,
    const float* __restrict__ W1, const float* __restrict__ W2,
    const float* __restrict__ b1, const float* __restrict__ b2)
{
    extern __shared__ char sm[];
    const uint32_t sb = s2u(sm);
    const int tid  = threadIdx.x;
    const int wid  = tid >> 5;
    const int lane = tid & 31;

    const int mBase = blockIdx.x * 128;
    const int nBase = blockIdx.y * 128;

    const float* __restrict__ Wsrc = (nBase < 512) ? W1 : W2;
    const int nOff = nBase & 511;

    const int wm = wid & 1;
    const int wn = wid >> 1;

    const int lr  = lane & 7;
    const int ls3 = (lane >> 3) & 1;
    const int ls4 = (lane >> 4) & 1;

    float acc[4][4][4];
#pragma unroll
    for (int mi = 0; mi < 4; mi++)
#pragma unroll
        for (int ni = 0; ni < 4; ni++)
#pragma unroll
            for (int f = 0; f < 4; f++) acc[mi][ni][f] = 0.0f;

    for (int kc = 0; kc < 8; kc++) {
        __syncthreads();

        float4 va[8];
#pragma unroll
        for (int t = 0; t < 8; t++) {
            int idx = tid + t * 256;
            int row = idx >> 4;
            int c4  = idx & 15;
            va[t] = *(const float4*)(x + (size_t)(mBase + row) * 512 + kc * 64 + c4 * 4);
        }
        float4 vb[8];
#pragma unroll
        for (int t = 0; t < 8; t++) {
            int idx = tid + t * 256;
            int row = idx >> 4;
            int c4  = idx & 15;
            vb[t] = *(const float4*)(Wsrc + (size_t)(nOff + row) * 512 + kc * 64 + c4 * 4);
        }
#pragma unroll
        for (int t = 0; t < 8; t++) {
            int idx = tid + t * 256;
            int row = idx >> 4;
            int c4  = idx & 15;
            uint32_t off = row * ROWB + c4 * 8;
            uint2 hh, ll;
            split4(va[t], hh, ll);
            *(uint2*)(sm + SM_AH + off) = hh;
            *(uint2*)(sm + SM_AL + off) = ll;
        }
#pragma unroll
        for (int t = 0; t < 8; t++) {
            int idx = tid + t * 256;
            int row = idx >> 4;
            int c4  = idx & 15;
            uint32_t off = row * ROWB + c4 * 8;
            uint2 hh, ll;
            split4(vb[t], hh, ll);
            *(uint2*)(sm + SM_BH + off) = hh;
            *(uint2*)(sm + SM_BL + off) = ll;
        }
        __syncthreads();

#pragma unroll
        for (int ks = 0; ks < 4; ks++) {
            const int kb = ks * 16;
            uint32_t aoff = (uint32_t)((wm * 64 + ls3 * 8 + lr) * ROWB + (kb + ls4 * 8) * 2);
            uint32_t boff = (uint32_t)((wn * 32 + ls4 * 8 + lr) * ROWB + (kb + ls3 * 8) * 2);

            uint32_t bhf[4][2], blf[4][2];
#pragma unroll
            for (int nb = 0; nb < 2; nb++) {
                LDM_X4(bhf[2 * nb][0], bhf[2 * nb][1], bhf[2 * nb + 1][0], bhf[2 * nb + 1][1],
                       sb + SM_BH + boff + nb * 16 * ROWB);
                LDM_X4(blf[2 * nb][0], blf[2 * nb][1], blf[2 * nb + 1][0], blf[2 * nb + 1][1],
                       sb + SM_BL + boff + nb * 16 * ROWB);
            }

            uint32_t af[4][4];
#pragma unroll
            for (int mi = 0; mi < 4; mi++)
                LDM_X4(af[mi][0], af[mi][1], af[mi][2], af[mi][3],
                       sb + SM_AH + aoff + mi * 16 * ROWB);
#pragma unroll
            for (int mi = 0; mi < 4; mi++)
#pragma unroll
                for (int ni = 0; ni < 4; ni++)
                    MMA_BF16(acc[mi][ni], af[mi], bhf[ni]);
#pragma unroll
            for (int mi = 0; mi < 4; mi++)
#pragma unroll
                for (int ni = 0; ni < 4; ni++)
                    MMA_BF16(acc[mi][ni], af[mi], blf[ni]);
#pragma unroll
            for (int mi = 0; mi < 4; mi++)
                LDM_X4(af[mi][0], af[mi][1], af[mi][2], af[mi][3],
                       sb + SM_AL + aoff + mi * 16 * ROWB);
#pragma unroll
            for (int mi = 0; mi < 4; mi++)
#pragma unroll
                for (int ni = 0; ni < 4; ni++)
                    MMA_BF16(acc[mi][ni], af[mi], bhf[ni]);
        }
    }

    const float* bias = (nBase < 512) ? (b1 + nBase) : (b2 + (nBase - 512));
#pragma unroll
    for (int mi = 0; mi < 4; mi++) {
#pragma unroll
        for (int ni = 0; ni < 4; ni++) {
            int m = mBase + wm * 64 + mi * 16 + (lane >> 2);
            int nl = wn * 32 + ni * 8 + (lane & 3) * 2;
            float bv0 = __ldg(bias + nl);
            float bv1 = __ldg(bias + nl + 1);
            float2 o0, o1;
            o0.x = tanhf(acc[mi][ni][0] + bv0);
            o0.y = tanhf(acc[mi][ni][1] + bv1);
            o1.x = tanhf(acc[mi][ni][2] + bv0);
            o1.y = tanhf(acc[mi][ni][3] + bv1);
            *(float2*)(g_y + (size_t)m * 1024 + nBase + nl)       = o0;
            *(float2*)(g_y + (size_t)(m + 8) * 1024 + nBase + nl) = o1;
        }
    }
}

// ---------------------------------------------------------------------------
// Phase 2: additive attention (R12 launch config — grid 256, no atomics).
// Inner loop restructured for ILP: per unrolled step, ALL group denominators/
// numerators are computed first, then ALL RCPs issue back-to-back, then the
// dependent fmas — ~8 independent chains in flight so one warp covers the
// 16-cyc MUFU latency (occupancy attempts in R12/R13 proved warp count is
// not the lever; chain exposure is).
// ---------------------------------------------------------------------------
#define ACH   64
#define STRJ  34
#define STRI  68
#define AT_SMEM ((2 * ACH * STRJ + ACH * STRI + ACH) * 4)   // 35072 B

__global__ __launch_bounds__(256, 2) void attn_kernel(
    const float* __restrict__ Wout,
    const float* __restrict__ bout,
    float* __restrict__ out)
{
    extern __shared__ float smf[];
    float* s_p  = smf;                           // [ACH][STRJ]
    float* s_wp = smf + ACH * STRJ;              // [ACH][STRJ]
    float* s_u  = smf + 2 * ACH * STRJ;          // [ACH][STRI]
    float* s_w  = s_u + ACH * STRI;              // [ACH]

    const int b  = blockIdx.z;
    const int j0 = blockIdx.x * 32;
    const int i0 = blockIdx.y * 64;

    const int tid = threadIdx.x;
    const int jg  = tid & 15;          // j = j0 + 2*jg + {0,1}
    const int ig  = tid >> 4;          // i = i0 + 4*ig + {0..3}

    const float* __restrict__ Y = g_y + (size_t)b * 128 * 1024;

    const int fa = tid & 63;
    const int fr = tid >> 6;

    const uint64_t ONE2 = 0x3F8000003F800000ull;
    uint64_t acc2[2][2] = {{0ull, 0ull}, {0ull, 0ull}};

    for (int cc = 0; cc < 8; cc++) {
        const int ac = cc * ACH;
        const float w = __ldg(Wout + ac + fa);

        __syncthreads();
#pragma unroll
        for (int t = 0; t < 8; t++) {
            int r = fr + t * 4;
            float p = Y[(size_t)(j0 + r) * 1024 + ac + fa];
            s_p [fa * STRJ + r] = p;
            s_wp[fa * STRJ + r] = w * p;
        }
#pragma unroll
        for (int t = 0; t < 16; t++) {
            int r  = fr + t * 4;
            int r2 = i0 + r + 1;
            r2 = (r2 > 127) ? 127 : r2;
            s_u[fa * STRI + r] = Y[(size_t)r2 * 1024 + 512 + ac + fa];
        }
        if (tid < ACH) s_w[tid] = w;
        __syncthreads();

        // a-quad per step: 2 a-pairs (A,B) and (C,D) processed together.
#pragma unroll 2
        for (int aq = 0; aq < ACH; aq += 4) {
            // ---- stage 1: load + broadcast everything for 8 groups ----
            uint64_t den[8], num[8], tt[4];
            {
                float2 wp01 = *(const float2*)&s_w[aq];
                float2 wp23 = *(const float2*)&s_w[aq + 2];
                uint64_t pb[4][2], wpb[4][2], up[4][2], wub[4][2];
#pragma unroll
                for (int s = 0; s < 4; s++) {
                    float2 pv  = *(const float2*)&s_p [(aq + s) * STRJ + jg * 2];
                    float2 wpv = *(const float2*)&s_wp[(aq + s) * STRJ + jg * 2];
                    ulonglong2 uv = *(const ulonglong2*)&s_u[(aq + s) * STRI + ig * 4];
                    pb[s][0]  = bcast2(pv.x);  pb[s][1]  = bcast2(pv.y);
                    wpb[s][0] = bcast2(wpv.x); wpb[s][1] = bcast2(wpv.y);
                    up[s][0] = uv.x; up[s][1] = uv.y;
                    float ws = (s == 0) ? wp01.x : (s == 1) ? wp01.y
                             : (s == 2) ? wp23.x : wp23.y;
                    uint64_t wb = bcast2(ws);
                    wub[s][0] = mul2(wb, uv.x);
                    wub[s][1] = mul2(wb, uv.y);
                }
                // groups: g = j*2 + ip over pairs (aq,aq+1); g+4 for (aq+2,aq+3)
#pragma unroll
                for (int j = 0; j < 2; j++)
#pragma unroll
                    for (int ip = 0; ip < 2; ip++) {
                        int g = j * 2 + ip;
                        uint64_t d1 = fma2(up[0][ip], pb[0][j], ONE2);
                        uint64_t d2 = fma2(up[1][ip], pb[1][j], ONE2);
                        uint64_t n1 = add2(wub[0][ip], wpb[0][j]);
                        uint64_t n2 = add2(wub[1][ip], wpb[1][j]);
                        den[g]   = d1;
                        num[g]   = mul2(n1, d2);
                        num[g]   = fma2(n2, d1, num[g]);
                        den[g]   = mul2(d1, d2);
                        uint64_t d3 = fma2(up[2][ip], pb[2][j], ONE2);
                        uint64_t d4 = fma2(up[3][ip], pb[3][j], ONE2);
                        uint64_t n3 = add2(wub[2][ip], wpb[2][j]);
                        uint64_t n4 = add2(wub[3][ip], wpb[3][j]);
                        num[g + 4] = mul2(n3, d4);
                        num[g + 4] = fma2(n4, d3, num[g + 4]);
                        den[g + 4] = mul2(d3, d4);
                    }
            }
            // ---- stage 2: all 16 rcps back-to-back ----
#pragma unroll
            for (int g = 0; g < 4; g++) {
                float2 taf = unpack2(den[g]);
                float2 tbf = unpack2(den[g + 4]);
                float ra0 = frcp(taf.x), ra1 = frcp(taf.y);
                float rb0 = frcp(tbf.x), rb1 = frcp(tbf.y);
                den[g]     = pack2(ra0, ra1);
                den[g + 4] = pack2(rb0, rb1);
                (void)tt;
            }
            // ---- stage 3: accumulate ----
#pragma unroll
            for (int j = 0; j < 2; j++)
#pragma unroll
                for (int ip = 0; ip < 2; ip++) {
                    int g = j * 2 + ip;
                    acc2[j][ip] = fma2(num[g],     den[g],     acc2[j][ip]);
                    acc2[j][ip] = fma2(num[g + 4], den[g + 4], acc2[j][ip]);
                }
        }
    }

    const float bo = __ldg(bout);
#pragma unroll
    for (int ip = 0; ip < 2; ip++) {
        float2 aj0 = unpack2(acc2[0][ip]);
        float2 aj1 = unpack2(acc2[1][ip]);
#pragma unroll
        for (int l = 0; l < 2; l++) {
            int i = i0 + ig * 4 + ip * 2 + l;
            if (i < 127) {
                float2 o;
                o.x = (l == 0 ? aj0.x : aj0.y) + bo;
                o.y = (l == 0 ? aj1.x : aj1.y) + bo;
                *(float2*)(out + ((size_t)b * 127 + i) * 128 + j0 + jg * 2) = o;
            }
        }
    }
}

// ---------------------------------------------------------------------------
extern "C" void kernel_launch(void* const* d_in, const int* in_sizes, int n_in,
                              void* d_out, int out_size)
{
    const float* x    = (const float*)d_in[0];
    const float* W1   = (const float*)d_in[1];
    const float* b1   = (const float*)d_in[2];
    const float* W2   = (const float*)d_in[3];
    const float* b2   = (const float*)d_in[4];
    const float* Wout = (const float*)d_in[5];
    const float* bout = (const float*)d_in[6];
    float* out = (float*)d_out;

    static bool attr_set = false;
    if (!attr_set) {
        cudaFuncSetAttribute(gemm_tc_kernel,
                             cudaFuncAttributeMaxDynamicSharedMemorySize, SM_TOTAL);
        cudaFuncSetAttribute(attn_kernel,
                             cudaFuncAttributeMaxDynamicSharedMemorySize, AT_SMEM);
        attr_set = true;
    }

    gemm_tc_kernel<<<dim3(32, 8), 256, SM_TOTAL>>>(x, W1, W2, b1, b2);

    attn_kernel<<<dim3(4, 2, 32), 256, AT_SMEM>>>(Wout, bout, out);
}